// round 12
// baseline (speedup 1.0000x reference)
#include <cuda_runtime.h>
#include <cuda_bf16.h>
#include <cstdint>

#define SLEN 512
#define BB   8
#define HH   16
#define DD   1024
#define WD   64

// Scratch (device globals — no allocation allowed in kernel_launch)
__device__ float g_Q [HH*BB*SLEN*WD];   // [h][m=b*512+i][w]
__device__ float g_K [HH*BB*SLEN*WD];
__device__ float g_V [HH*BB*SLEN*WD];
__device__ float g_PK[HH*2*SLEN*WD];    // [h][r][w]
__device__ float g_PQ[HH*2*SLEN*WD];
// Bias tables (bf16): [h][m(4096)][r(1024)]
__device__ __nv_bfloat16 g_C2P[(size_t)HH*4096*1024];
__device__ __nv_bfloat16 g_P2C[(size_t)HH*4096*1024];

// ===========================================================================
// mma.sync bf16 helpers (sm_80+, compiles for plain sm_100)
// ===========================================================================
__device__ __forceinline__ void mma_bf16(float* d,
    uint32_t a0, uint32_t a1, uint32_t a2, uint32_t a3,
    uint32_t b0, uint32_t b1)
{
    asm volatile(
        "mma.sync.aligned.m16n8k16.row.col.f32.bf16.bf16.f32 "
        "{%0,%1,%2,%3}, {%4,%5,%6,%7}, {%8,%9}, {%0,%1,%2,%3};"
        : "+f"(d[0]), "+f"(d[1]), "+f"(d[2]), "+f"(d[3])
        : "r"(a0), "r"(a1), "r"(a2), "r"(a3), "r"(b0), "r"(b1));
}
__device__ __forceinline__ uint32_t pack_bf16(float a, float b) {
    __nv_bfloat162 h = __floats2bfloat162_rn(a, b);
    return *reinterpret_cast<uint32_t*>(&h);
}
__device__ __forceinline__ float bf16_hi(float a) {
    return __bfloat162float(__float2bfloat16_rn(a));
}
__device__ __forceinline__ float ex2f(float x) {
    float r;
    asm("ex2.approx.f32 %0, %1;" : "=f"(r) : "f"(x));
    return r;
}

// ===========================================================================
// Projection GEMM (round-8 mainloop/epilogue, yoff selects n-block range):
//   C[5120,3072] = [x(4096); re(1024)] @ [Wq|Wk|Wv]^T  (+bias), scatter store.
// ===========================================================================
#define P_PITCH 20
#define P_ARR   (128*P_PITCH)
#define P_SMEM_WORDS (2*4*P_ARR)
#define P_SMEM_BYTES (P_SMEM_WORDS*4)    // 81920

__global__ __launch_bounds__(256, 1) void proj_mma_kernel(
    const float* __restrict__ x, const float* __restrict__ re,
    const float* __restrict__ Wq, const float* __restrict__ bq,
    const float* __restrict__ Wk, const float* __restrict__ bk,
    const float* __restrict__ Wv, const float* __restrict__ bv,
    float* __restrict__ outQ, float* __restrict__ outK, float* __restrict__ outV,
    float* __restrict__ outPK, float* __restrict__ outPQ, int yoff)
{
    extern __shared__ uint32_t smw[];
    const int m0 = blockIdx.x * 128;
    const int n0 = (blockIdx.y + yoff) * 128;
    const bool isRe = (m0 >= 4096);
    const int nreg = n0 >> 10;
    if (isRe && nreg == 2) return;

    const int tid  = threadIdx.x;
    const int lane = tid & 31;
    const int wid  = tid >> 5;
    const int wm   = wid >> 2;
    const int wn   = wid & 3;

    const float* Ag = isRe ? (re + (size_t)(m0 - 4096) * DD) : (x + (size_t)m0 * DD);
    const float* Wg = ((nreg == 0) ? Wq : (nreg == 1) ? Wk : Wv) + (size_t)(n0 & 1023) * DD;

    const int srow[4] = { tid >> 3, (tid + 256) >> 3, (tid + 512) >> 3, (tid + 768) >> 3 };
    const int sf4  = tid & 7;

    float acc[4][4][4] = {};
    float4 sa[4], sw4[4];

    #pragma unroll
    for (int j = 0; j < 4; j++) {
        sa[j]  = *(const float4*)(Ag + (size_t)srow[j]*DD + sf4*4);
        sw4[j] = *(const float4*)(Wg + (size_t)srow[j]*DD + sf4*4);
    }
    {
        uint32_t* Ah = smw;             uint32_t* Al = smw + P_ARR;
        uint32_t* Wh = smw + 2*P_ARR;   uint32_t* Wl = smw + 3*P_ARR;
        #pragma unroll
        for (int j = 0; j < 4; j++) {
            int wbase = srow[j]*P_PITCH + sf4*2;
            float4 v = sa[j];
            Ah[wbase]   = pack_bf16(v.x, v.y);
            Ah[wbase+1] = pack_bf16(v.z, v.w);
            Al[wbase]   = pack_bf16(v.x - bf16_hi(v.x), v.y - bf16_hi(v.y));
            Al[wbase+1] = pack_bf16(v.z - bf16_hi(v.z), v.w - bf16_hi(v.w));
            v = sw4[j];
            Wh[wbase]   = pack_bf16(v.x, v.y);
            Wh[wbase+1] = pack_bf16(v.z, v.w);
            Wl[wbase]   = pack_bf16(v.x - bf16_hi(v.x), v.y - bf16_hi(v.y));
            Wl[wbase+1] = pack_bf16(v.z - bf16_hi(v.z), v.w - bf16_hi(v.w));
        }
    }
    __syncthreads();

    for (int c = 0; c < 32; c++) {
        const int buf = c & 1;
        if (c + 1 < 32) {
            const int kc = (c + 1) * 32;
            #pragma unroll
            for (int j = 0; j < 4; j++) {
                sa[j]  = *(const float4*)(Ag + (size_t)srow[j]*DD + kc + sf4*4);
                sw4[j] = *(const float4*)(Wg + (size_t)srow[j]*DD + kc + sf4*4);
            }
        }
        {
            const uint32_t* Ah = smw + (buf*4 + 0)*P_ARR;
            const uint32_t* Al = smw + (buf*4 + 1)*P_ARR;
            const uint32_t* Wh = smw + (buf*4 + 2)*P_ARR;
            const uint32_t* Wl = smw + (buf*4 + 3)*P_ARR;
            #pragma unroll
            for (int ks = 0; ks < 2; ks++) {
                const int kw = (lane & 3) + ks*8;
                uint32_t ah[4][4], al[4][4];
                #pragma unroll
                for (int mt = 0; mt < 4; mt++) {
                    int r = wm*64 + mt*16 + (lane >> 2);
                    int b0 = r*P_PITCH + kw;
                    ah[mt][0] = Ah[b0];       ah[mt][1] = Ah[b0 + 8*P_PITCH];
                    ah[mt][2] = Ah[b0 + 4];   ah[mt][3] = Ah[b0 + 8*P_PITCH + 4];
                    al[mt][0] = Al[b0];       al[mt][1] = Al[b0 + 8*P_PITCH];
                    al[mt][2] = Al[b0 + 4];   al[mt][3] = Al[b0 + 8*P_PITCH + 4];
                }
                uint32_t bh[4][2], bl[4][2];
                #pragma unroll
                for (int nt = 0; nt < 4; nt++) {
                    int rn = wn*32 + nt*8 + (lane >> 2);
                    int b0 = rn*P_PITCH + kw;
                    bh[nt][0] = Wh[b0]; bh[nt][1] = Wh[b0 + 4];
                    bl[nt][0] = Wl[b0]; bl[nt][1] = Wl[b0 + 4];
                }
                #pragma unroll
                for (int mt = 0; mt < 4; mt++)
                    #pragma unroll
                    for (int nt = 0; nt < 4; nt++) {
                        mma_bf16(acc[mt][nt], ah[mt][0], ah[mt][1], ah[mt][2], ah[mt][3],
                                 bh[nt][0], bh[nt][1]);
                        mma_bf16(acc[mt][nt], ah[mt][0], ah[mt][1], ah[mt][2], ah[mt][3],
                                 bl[nt][0], bl[nt][1]);
                        mma_bf16(acc[mt][nt], al[mt][0], al[mt][1], al[mt][2], al[mt][3],
                                 bh[nt][0], bh[nt][1]);
                    }
            }
        }
        if (c + 1 < 32) {
            const int ob = 1 - buf;
            uint32_t* Ah = smw + (ob*4 + 0)*P_ARR;
            uint32_t* Al = smw + (ob*4 + 1)*P_ARR;
            uint32_t* Wh = smw + (ob*4 + 2)*P_ARR;
            uint32_t* Wl = smw + (ob*4 + 3)*P_ARR;
            #pragma unroll
            for (int j = 0; j < 4; j++) {
                int wbase = srow[j]*P_PITCH + sf4*2;
                float4 v = sa[j];
                Ah[wbase]   = pack_bf16(v.x, v.y);
                Ah[wbase+1] = pack_bf16(v.z, v.w);
                Al[wbase]   = pack_bf16(v.x - bf16_hi(v.x), v.y - bf16_hi(v.y));
                Al[wbase+1] = pack_bf16(v.z - bf16_hi(v.z), v.w - bf16_hi(v.w));
                v = sw4[j];
                Wh[wbase]   = pack_bf16(v.x, v.y);
                Wh[wbase+1] = pack_bf16(v.z, v.w);
                Wl[wbase]   = pack_bf16(v.x - bf16_hi(v.x), v.y - bf16_hi(v.y));
                Wl[wbase+1] = pack_bf16(v.z - bf16_hi(v.z), v.w - bf16_hi(v.w));
            }
        }
        __syncthreads();
    }

    const float* bp = (nreg == 0) ? bq : (nreg == 1) ? bk : bv;
    float* baseO;
    int Mrows, moff;
    if (!isRe) {
        baseO = (nreg == 0) ? outQ : (nreg == 1) ? outK : outV;
        Mrows = 4096; moff = m0;
    } else {
        baseO = (nreg == 0) ? outPQ : outPK;
        Mrows = 1024; moff = m0 - 4096;
    }

    #pragma unroll
    for (int mt = 0; mt < 4; mt++) {
        int m = moff + wm*64 + mt*16 + (lane >> 2);
        #pragma unroll
        for (int nt = 0; nt < 4; nt++) {
            int ncl = (n0 & 1023) + wn*32 + nt*8 + (lane & 3)*2;
            int hh = ncl >> 6, w = ncl & 63;
            float bx = bp[ncl], by = bp[ncl + 1];
            float* d0 = baseO + ((size_t)hh*Mrows + m)*64 + w;
            float2 v0 = { acc[mt][nt][0] + bx, acc[mt][nt][1] + by };
            float2 v1 = { acc[mt][nt][2] + bx, acc[mt][nt][3] + by };
            *(float2*)d0 = v0;
            *(float2*)(d0 + 8*64) = v1;
        }
    }
}

// ===========================================================================
// Bias table GEMM — single bf16 product, bf16 output. hoff selects head half.
//   tbl 0: C2P[h,m,r] = Q[h,m,:]·PK[h,r,:];  tbl 1: P2C = K·PQ
// grid (32, 8, 16): z = (h - hoff) + 8*tbl
// ===========================================================================
#define T_PITCH 36
#define T_ARR   (128*T_PITCH)
#define T_SMEM_BYTES (2*T_ARR*4)         // 36864

__global__ __launch_bounds__(256) void bias_table_kernel(int hoff)
{
    extern __shared__ uint32_t smw[];
    const int m0 = blockIdx.x * 128;     // [0,4096)
    const int n0 = blockIdx.y * 128;     // [0,1024)
    const int h   = (blockIdx.z & 7) + hoff;
    const int tbl = blockIdx.z >> 3;

    const int tid  = threadIdx.x;
    const int lane = tid & 31;
    const int wid  = tid >> 5;
    const int wm   = wid >> 2;
    const int wn   = wid & 3;

    const float* Ag = (tbl ? g_K : g_Q) + ((size_t)h*4096 + m0) * WD;
    const float* Bg = (tbl ? g_PQ : g_PK) + ((size_t)h*1024 + n0) * WD;
    __nv_bfloat16* Cg = (tbl ? g_P2C : g_C2P) + (size_t)h*4096*1024;

    uint32_t* Ah = smw;
    uint32_t* Bh = smw + T_ARR;

    #pragma unroll
    for (int v = 0; v < 8; v++) {
        int idx = v*256 + tid;
        int row = idx >> 4;
        int cw  = idx & 15;
        int wbase = row*T_PITCH + cw*2;
        float4 a = *(const float4*)(Ag + (size_t)row*WD + cw*4);
        Ah[wbase]   = pack_bf16(a.x, a.y);
        Ah[wbase+1] = pack_bf16(a.z, a.w);
        float4 b = *(const float4*)(Bg + (size_t)row*WD + cw*4);
        Bh[wbase]   = pack_bf16(b.x, b.y);
        Bh[wbase+1] = pack_bf16(b.z, b.w);
    }
    __syncthreads();

    float acc[4][4][4] = {};
    #pragma unroll
    for (int ks = 0; ks < 4; ks++) {
        const int kw = (lane & 3) + ks*8;
        uint32_t ah[4][4];
        #pragma unroll
        for (int mt = 0; mt < 4; mt++) {
            int r = wm*64 + mt*16 + (lane >> 2);
            int b0 = r*T_PITCH + kw;
            ah[mt][0] = Ah[b0];       ah[mt][1] = Ah[b0 + 8*T_PITCH];
            ah[mt][2] = Ah[b0 + 4];   ah[mt][3] = Ah[b0 + 8*T_PITCH + 4];
        }
        uint32_t bh[4][2];
        #pragma unroll
        for (int nt = 0; nt < 4; nt++) {
            int rn = wn*32 + nt*8 + (lane >> 2);
            int b0 = rn*T_PITCH + kw;
            bh[nt][0] = Bh[b0]; bh[nt][1] = Bh[b0 + 4];
        }
        #pragma unroll
        for (int mt = 0; mt < 4; mt++)
            #pragma unroll
            for (int nt = 0; nt < 4; nt++)
                mma_bf16(acc[mt][nt], ah[mt][0], ah[mt][1], ah[mt][2], ah[mt][3],
                         bh[nt][0], bh[nt][1]);
    }

    #pragma unroll
    for (int mt = 0; mt < 4; mt++) {
        int m = m0 + wm*64 + mt*16 + (lane >> 2);
        #pragma unroll
        for (int nt = 0; nt < 4; nt++) {
            int ncl = n0 + wn*32 + nt*8 + (lane & 3)*2;
            __nv_bfloat16* d0 = Cg + (size_t)m*1024 + ncl;
            *(uint32_t*)d0 = pack_bf16(acc[mt][nt][0], acc[mt][nt][1]);
            *(uint32_t*)(d0 + 8*1024) = pack_bf16(acc[mt][nt][2], acc[mt][nt][3]);
        }
    }
}

// ===========================================================================
// HMMA flash attention, occupancy-3 (round-8/11, known good). hoff = head half.
// CTA = 64 i-rows (4 warps, m16 each), 128 threads, smem 70.7 KB.
// ===========================================================================
#define AQ_P 36
#define CP_P 66
#define W_KH 0
#define W_KL (W_KH + 64*AQ_P)            // 2304
#define W_VH (W_KL + 64*AQ_P)            // 4608
#define W_VL (W_VH + 64*AQ_P)            // 6912
#define W_C2 (W_VL + 64*AQ_P)            // 9216  (fp32 [di][jl] pitch 66)
#define W_P2 (W_C2 + 64*CP_P)            // 13440 (fp32 [jl][di] pitch 66)
#define ATTN_WORDS (W_P2 + 64*CP_P)      // 17664
#define ATTN_SMEM_BYTES (ATTN_WORDS*4)   // 70656
#define W_QH W_C2
#define W_QL (W_C2 + 64*AQ_P)

__global__ __launch_bounds__(128, 3) void attn_mma_kernel(float* __restrict__ out, int hoff)
{
    extern __shared__ uint32_t smw[];
    float* fC2P = (float*)(smw + W_C2);
    float* fP2C = (float*)(smw + W_P2);

    const int h  = blockIdx.z + hoff;
    const int b  = blockIdx.y;
    const int i0 = blockIdx.x * 64;
    const int tid  = threadIdx.x;
    const int lane = tid & 31;
    const int warp = tid >> 5;     // 0..3
    const int g = lane >> 2;       // row within m16 half
    const int t = lane & 3;        // col quad index

    const float* Qg  = g_Q + ((size_t)(h*BB + b)*SLEN + i0)*WD;
    const float* Kg  = g_K + (size_t)(h*BB + b)*SLEN*WD;
    const float* Vg  = g_V + (size_t)(h*BB + b)*SLEN*WD;
    const __nv_bfloat16* C2Pg = g_C2P + ((size_t)h*4096 + (size_t)b*512)*1024;
    const __nv_bfloat16* P2Cg = g_P2C + ((size_t)h*4096 + (size_t)b*512)*1024;

    // ---- Stage Q (aliased region) and cache a-fragments ----
    for (int idx = tid; idx < 1024; idx += 128) {
        int r = idx >> 4, c4 = (idx & 15) << 2;
        float4 v = *(const float4*)(Qg + r*WD + c4);
        int wb = r*AQ_P + (c4 >> 1);
        smw[W_QH + wb]     = pack_bf16(v.x, v.y);
        smw[W_QH + wb + 1] = pack_bf16(v.z, v.w);
        smw[W_QL + wb]     = pack_bf16(v.x - bf16_hi(v.x), v.y - bf16_hi(v.y));
        smw[W_QL + wb + 1] = pack_bf16(v.z - bf16_hi(v.z), v.w - bf16_hi(v.w));
    }
    __syncthreads();

    uint32_t qh[4][4], ql[4][4];
    {
        const int r0w = (16*warp + g)*AQ_P;
        const int r1w = (16*warp + g + 8)*AQ_P;
        #pragma unroll
        for (int ks = 0; ks < 4; ks++) {
            int o0 = 8*ks + t;
            qh[ks][0] = smw[W_QH + r0w + o0];     qh[ks][1] = smw[W_QH + r1w + o0];
            qh[ks][2] = smw[W_QH + r0w + o0 + 4]; qh[ks][3] = smw[W_QH + r1w + o0 + 4];
            ql[ks][0] = smw[W_QL + r0w + o0];     ql[ks][1] = smw[W_QL + r1w + o0];
            ql[ks][2] = smw[W_QL + r0w + o0 + 4]; ql[ks][3] = smw[W_QL + r1w + o0 + 4];
        }
    }

    float o[8][4] = {};
    float m0 = -1e30f, m1 = -1e30f, l0 = 0.f, l1 = 0.f;
    const float L2S = rsqrtf(192.0f) * 1.44269504f;
    const int r0 = 16*warp + g;

    for (int jt = 0; jt < 8; jt++) {
        const int j0 = jt * 64;
        __syncthreads();   // prior tile reads complete (covers Q frag load at jt=0)

        // K hi/lo [j][w-pairs]
        for (int idx = tid; idx < 1024; idx += 128) {
            int r = idx >> 4, c4 = (idx & 15) << 2;
            float4 v = *(const float4*)(Kg + (j0 + r)*WD + c4);
            int wb = r*AQ_P + (c4 >> 1);
            smw[W_KH + wb]     = pack_bf16(v.x, v.y);
            smw[W_KH + wb + 1] = pack_bf16(v.z, v.w);
            smw[W_KL + wb]     = pack_bf16(v.x - bf16_hi(v.x), v.y - bf16_hi(v.y));
            smw[W_KL + wb + 1] = pack_bf16(v.z - bf16_hi(v.z), v.w - bf16_hi(v.w));
        }
        // V transposed hi/lo [w][j-pairs]
        for (int idx = tid; idx < 512; idx += 128) {
            int jp = idx & 31, c4 = (idx >> 5) << 2;
            const float* v0p = Vg + (j0 + 2*jp)*WD + c4;
            float4 a = *(const float4*)v0p;
            float4 c = *(const float4*)(v0p + WD);
            smw[W_VH + (c4+0)*AQ_P + jp] = pack_bf16(a.x, c.x);
            smw[W_VH + (c4+1)*AQ_P + jp] = pack_bf16(a.y, c.y);
            smw[W_VH + (c4+2)*AQ_P + jp] = pack_bf16(a.z, c.z);
            smw[W_VH + (c4+3)*AQ_P + jp] = pack_bf16(a.w, c.w);
            smw[W_VL + (c4+0)*AQ_P + jp] = pack_bf16(a.x - bf16_hi(a.x), c.x - bf16_hi(c.x));
            smw[W_VL + (c4+1)*AQ_P + jp] = pack_bf16(a.y - bf16_hi(a.y), c.y - bf16_hi(c.y));
            smw[W_VL + (c4+2)*AQ_P + jp] = pack_bf16(a.z - bf16_hi(a.z), c.z - bf16_hi(c.z));
            smw[W_VL + (c4+3)*AQ_P + jp] = pack_bf16(a.w - bf16_hi(a.w), c.w - bf16_hi(c.w));
        }
        // C2P gather [di][jl] (reversed-j bf16 reads)
        for (int idx = tid; idx < 1024; idx += 128) {
            int di = idx >> 4, jg = idx & 15;
            const __nv_bfloat16* src = C2Pg + (size_t)(i0 + di)*1024
                                       + (i0 + di) - j0 + 511 - 4*jg;
            float* dst = fC2P + di*CP_P + 4*jg;
            dst[0] = __bfloat162float(src[0]);
            dst[1] = __bfloat162float(src[-1]);
            dst[2] = __bfloat162float(src[-2]);
            dst[3] = __bfloat162float(src[-3]);
        }
        // P2C gather [jl][di] (contiguous along di)
        for (int idx = tid; idx < 4096; idx += 128) {
            int jl = idx >> 6, di = idx & 63;
            fP2C[jl*CP_P + di] = __bfloat162float(
                P2Cg[(size_t)(j0 + jl)*1024 + i0 - j0 - jl + 511 + di]);
        }
        __syncthreads();

        // ---- S = Q K^T (split bf16, 3 products) ----
        float s[8][4];
        #pragma unroll
        for (int nt = 0; nt < 8; nt++) {
            float c[4] = {0.f, 0.f, 0.f, 0.f};
            #pragma unroll
            for (int ks = 0; ks < 4; ks++) {
                int kb = (8*nt + g)*AQ_P + 8*ks + t;
                uint32_t bh0 = smw[W_KH + kb], bh1 = smw[W_KH + kb + 4];
                uint32_t bl0 = smw[W_KL + kb], bl1 = smw[W_KL + kb + 4];
                mma_bf16(c, qh[ks][0], qh[ks][1], qh[ks][2], qh[ks][3], bh0, bh1);
                mma_bf16(c, qh[ks][0], qh[ks][1], qh[ks][2], qh[ks][3], bl0, bl1);
                mma_bf16(c, ql[ks][0], ql[ks][1], ql[ks][2], ql[ks][3], bh0, bh1);
            }
            s[nt][0] = c[0]; s[nt][1] = c[1]; s[nt][2] = c[2]; s[nt][3] = c[3];
        }

        // ---- bias add + scale (log2 domain) ----
        #pragma unroll
        for (int nt = 0; nt < 8; nt++) {
            int cb = 8*nt + 2*t;
            float2 cA = *(const float2*)(fC2P + r0*CP_P + cb);
            float2 cB = *(const float2*)(fC2P + (r0+8)*CP_P + cb);
            float pA0 = fP2C[cb*CP_P + r0],     pA1 = fP2C[(cb+1)*CP_P + r0];
            float pB0 = fP2C[cb*CP_P + r0 + 8], pB1 = fP2C[(cb+1)*CP_P + r0 + 8];
            s[nt][0] = (s[nt][0] + cA.x + pA0) * L2S;
            s[nt][1] = (s[nt][1] + cA.y + pA1) * L2S;
            s[nt][2] = (s[nt][2] + cB.x + pB0) * L2S;
            s[nt][3] = (s[nt][3] + cB.y + pB1) * L2S;
        }

        // ---- online softmax (quad reduce) ----
        float mx0 = -1e30f, mx1 = -1e30f;
        #pragma unroll
        for (int nt = 0; nt < 8; nt++) {
            mx0 = fmaxf(mx0, fmaxf(s[nt][0], s[nt][1]));
            mx1 = fmaxf(mx1, fmaxf(s[nt][2], s[nt][3]));
        }
        mx0 = fmaxf(mx0, __shfl_xor_sync(0xffffffffu, mx0, 1));
        mx0 = fmaxf(mx0, __shfl_xor_sync(0xffffffffu, mx0, 2));
        mx1 = fmaxf(mx1, __shfl_xor_sync(0xffffffffu, mx1, 1));
        mx1 = fmaxf(mx1, __shfl_xor_sync(0xffffffffu, mx1, 2));
        float mn0 = fmaxf(m0, mx0), mn1 = fmaxf(m1, mx1);
        float cr0 = ex2f(m0 - mn0), cr1 = ex2f(m1 - mn1);
        float rs0 = 0.f, rs1 = 0.f;
        #pragma unroll
        for (int nt = 0; nt < 8; nt++) {
            s[nt][0] = ex2f(s[nt][0] - mn0);
            s[nt][1] = ex2f(s[nt][1] - mn0);
            s[nt][2] = ex2f(s[nt][2] - mn1);
            s[nt][3] = ex2f(s[nt][3] - mn1);
            rs0 += s[nt][0] + s[nt][1];
            rs1 += s[nt][2] + s[nt][3];
        }
        rs0 += __shfl_xor_sync(0xffffffffu, rs0, 1);
        rs0 += __shfl_xor_sync(0xffffffffu, rs0, 2);
        rs1 += __shfl_xor_sync(0xffffffffu, rs1, 1);
        rs1 += __shfl_xor_sync(0xffffffffu, rs1, 2);
        l0 = l0*cr0 + rs0;  l1 = l1*cr1 + rs1;
        m0 = mn0;  m1 = mn1;
        #pragma unroll
        for (int nt = 0; nt < 8; nt++) {
            o[nt][0] *= cr0; o[nt][1] *= cr0;
            o[nt][2] *= cr1; o[nt][3] *= cr1;
        }

        // ---- O += P V (C-frag -> A-frag in registers, 3 products) ----
        #pragma unroll
        for (int kt = 0; kt < 4; kt++) {
            float p00 = s[2*kt][0],   p01 = s[2*kt][1];
            float p02 = s[2*kt][2],   p03 = s[2*kt][3];
            float p10 = s[2*kt+1][0], p11 = s[2*kt+1][1];
            float p12 = s[2*kt+1][2], p13 = s[2*kt+1][3];
            uint32_t pa0 = pack_bf16(p00, p01), pa1 = pack_bf16(p02, p03);
            uint32_t pa2 = pack_bf16(p10, p11), pa3 = pack_bf16(p12, p13);
            uint32_t pl0 = pack_bf16(p00 - bf16_hi(p00), p01 - bf16_hi(p01));
            uint32_t pl1 = pack_bf16(p02 - bf16_hi(p02), p03 - bf16_hi(p03));
            uint32_t pl2 = pack_bf16(p10 - bf16_hi(p10), p11 - bf16_hi(p11));
            uint32_t pl3 = pack_bf16(p12 - bf16_hi(p12), p13 - bf16_hi(p13));
            #pragma unroll
            for (int nw = 0; nw < 8; nw++) {
                int vb = (8*nw + g)*AQ_P + 8*kt + t;
                uint32_t vh0 = smw[W_VH + vb], vh1 = smw[W_VH + vb + 4];
                uint32_t vl0 = smw[W_VL + vb], vl1 = smw[W_VL + vb + 4];
                mma_bf16(o[nw], pa0, pa1, pa2, pa3, vh0, vh1);
                mma_bf16(o[nw], pa0, pa1, pa2, pa3, vl0, vl1);
                mma_bf16(o[nw], pl0, pl1, pl2, pl3, vh0, vh1);
            }
        }
    }

    // ---- epilogue ----
    float inv0 = 1.0f / l0, inv1 = 1.0f / l1;
    #pragma unroll
    for (int nw = 0; nw < 8; nw++) {
        int wcol = h*64 + 8*nw + 2*t;
        float* d0 = out + ((size_t)b*SLEN + i0 + r0)*DD + wcol;
        *(float2*)d0 = make_float2(o[nw][0]*inv0, o[nw][1]*inv0);
        *(float2*)(d0 + 8*DD) = make_float2(o[nw][2]*inv1, o[nw][3]*inv1);
    }
}

// ===========================================================================
// Launch (half-split pipeline):
//   main: projA → tableA(h0-7) → wait(e2) → attnA(h0-7) → wait(e3) → attnB(h8-15)
//   s2:   wait(eF) → projV → e2 → tableB(h8-15) → e3
// ===========================================================================
extern "C" void kernel_launch(void* const* d_in, const int* in_sizes, int n_in,
                              void* d_out, int out_size)
{
    (void)in_sizes; (void)n_in; (void)out_size;
    const float* x  = (const float*)d_in[0];
    const float* re = (const float*)d_in[1];
    const float* Wq = (const float*)d_in[2];
    const float* bq = (const float*)d_in[3];
    const float* Wk = (const float*)d_in[4];
    const float* bk = (const float*)d_in[5];
    const float* Wv = (const float*)d_in[6];
    const float* bv = (const float*)d_in[7];
    float* out = (float*)d_out;

    void *qp, *kp, *vp, *pkp, *pqp;
    cudaGetSymbolAddress(&qp,  g_Q);
    cudaGetSymbolAddress(&kp,  g_K);
    cudaGetSymbolAddress(&vp,  g_V);
    cudaGetSymbolAddress(&pkp, g_PK);
    cudaGetSymbolAddress(&pqp, g_PQ);

    cudaFuncSetAttribute(proj_mma_kernel, cudaFuncAttributeMaxDynamicSharedMemorySize,
                         P_SMEM_BYTES);
    cudaFuncSetAttribute(bias_table_kernel, cudaFuncAttributeMaxDynamicSharedMemorySize,
                         T_SMEM_BYTES);
    cudaFuncSetAttribute(attn_mma_kernel, cudaFuncAttributeMaxDynamicSharedMemorySize,
                         ATTN_SMEM_BYTES);

    cudaStream_t s2;
    cudaEvent_t eFork, e2, e3;
    cudaStreamCreateWithFlags(&s2, cudaStreamNonBlocking);
    cudaEventCreateWithFlags(&eFork, cudaEventDisableTiming);
    cudaEventCreateWithFlags(&e2, cudaEventDisableTiming);
    cudaEventCreateWithFlags(&e3, cudaEventDisableTiming);

    // projA: Q,K projections + pos_q,pos_k (n-blocks 0..15, all 5120 rows)
    proj_mma_kernel<<<dim3(40, 16), dim3(256), P_SMEM_BYTES>>>(
        x, re, Wq, bq, Wk, bk, Wv, bv,
        (float*)qp, (float*)kp, (float*)vp, (float*)pkp, (float*)pqp, 0);

    cudaEventRecord(eFork, 0);
    cudaStreamWaitEvent(s2, eFork, 0);

    // s2: projV (n-blocks 16..23, x rows only), then tables for heads 8..15
    proj_mma_kernel<<<dim3(32, 8), dim3(256), P_SMEM_BYTES, s2>>>(
        x, re, Wq, bq, Wk, bk, Wv, bv,
        (float*)qp, (float*)kp, (float*)vp, (float*)pkp, (float*)pqp, 16);
    cudaEventRecord(e2, s2);
    bias_table_kernel<<<dim3(32, 8, 16), dim3(256), T_SMEM_BYTES, s2>>>(8);
    cudaEventRecord(e3, s2);

    // main: tables for heads 0..7 (needs only projA outputs)
    bias_table_kernel<<<dim3(32, 8, 16), dim3(256), T_SMEM_BYTES>>>(0);

    // attn for heads 0..7 (needs tableA + projV)
    cudaStreamWaitEvent(0, e2, 0);
    attn_mma_kernel<<<dim3(8, BB, 8), dim3(128), ATTN_SMEM_BYTES>>>(out, 0);

    // attn for heads 8..15 (needs tableB)
    cudaStreamWaitEvent(0, e3, 0);
    attn_mma_kernel<<<dim3(8, BB, 8), dim3(128), ATTN_SMEM_BYTES>>>(out, 8);
}

// round 13
// speedup vs baseline: 1.2297x; 1.2297x over previous
#include <cuda_runtime.h>
#include <cuda_bf16.h>
#include <cstdint>

#define SLEN 512
#define BB   8
#define HH   16
#define DD   1024
#define WD   64

// Scratch (device globals — no allocation allowed in kernel_launch)
__device__ float g_Q [HH*BB*SLEN*WD];   // [h][m=b*512+i][w]
__device__ float g_K [HH*BB*SLEN*WD];
__device__ float g_V [HH*BB*SLEN*WD];
__device__ float g_PK[HH*2*SLEN*WD];    // [h][r][w]
__device__ float g_PQ[HH*2*SLEN*WD];
// Bias tables (bf16): [h][m(4096)][r(1024)] — only the diagonal band is written/read
__device__ __nv_bfloat16 g_C2P[(size_t)HH*4096*1024];
__device__ __nv_bfloat16 g_P2C[(size_t)HH*4096*1024];

// ===========================================================================
// mma.sync bf16 helpers (sm_80+, compiles for plain sm_100)
// ===========================================================================
__device__ __forceinline__ void mma_bf16(float* d,
    uint32_t a0, uint32_t a1, uint32_t a2, uint32_t a3,
    uint32_t b0, uint32_t b1)
{
    asm volatile(
        "mma.sync.aligned.m16n8k16.row.col.f32.bf16.bf16.f32 "
        "{%0,%1,%2,%3}, {%4,%5,%6,%7}, {%8,%9}, {%0,%1,%2,%3};"
        : "+f"(d[0]), "+f"(d[1]), "+f"(d[2]), "+f"(d[3])
        : "r"(a0), "r"(a1), "r"(a2), "r"(a3), "r"(b0), "r"(b1));
}
__device__ __forceinline__ uint32_t pack_bf16(float a, float b) {
    __nv_bfloat162 h = __floats2bfloat162_rn(a, b);
    return *reinterpret_cast<uint32_t*>(&h);
}
__device__ __forceinline__ float bf16_hi(float a) {
    return __bfloat162float(__float2bfloat16_rn(a));
}
__device__ __forceinline__ float ex2f(float x) {
    float r;
    asm("ex2.approx.f32 %0, %1;" : "=f"(r) : "f"(x));
    return r;
}

// ===========================================================================
// Projection GEMM (round-8 mainloop/epilogue, yoff selects n-block range):
//   C[5120,3072] = [x(4096); re(1024)] @ [Wq|Wk|Wv]^T  (+bias), scatter store.
// ===========================================================================
#define P_PITCH 20
#define P_ARR   (128*P_PITCH)
#define P_SMEM_WORDS (2*4*P_ARR)
#define P_SMEM_BYTES (P_SMEM_WORDS*4)    // 81920

__global__ __launch_bounds__(256, 1) void proj_mma_kernel(
    const float* __restrict__ x, const float* __restrict__ re,
    const float* __restrict__ Wq, const float* __restrict__ bq,
    const float* __restrict__ Wk, const float* __restrict__ bk,
    const float* __restrict__ Wv, const float* __restrict__ bv,
    float* __restrict__ outQ, float* __restrict__ outK, float* __restrict__ outV,
    float* __restrict__ outPK, float* __restrict__ outPQ, int yoff)
{
    extern __shared__ uint32_t smw[];
    const int m0 = blockIdx.x * 128;
    const int n0 = (blockIdx.y + yoff) * 128;
    const bool isRe = (m0 >= 4096);
    const int nreg = n0 >> 10;
    if (isRe && nreg == 2) return;

    const int tid  = threadIdx.x;
    const int lane = tid & 31;
    const int wid  = tid >> 5;
    const int wm   = wid >> 2;
    const int wn   = wid & 3;

    const float* Ag = isRe ? (re + (size_t)(m0 - 4096) * DD) : (x + (size_t)m0 * DD);
    const float* Wg = ((nreg == 0) ? Wq : (nreg == 1) ? Wk : Wv) + (size_t)(n0 & 1023) * DD;

    const int srow[4] = { tid >> 3, (tid + 256) >> 3, (tid + 512) >> 3, (tid + 768) >> 3 };
    const int sf4  = tid & 7;

    float acc[4][4][4] = {};
    float4 sa[4], sw4[4];

    #pragma unroll
    for (int j = 0; j < 4; j++) {
        sa[j]  = *(const float4*)(Ag + (size_t)srow[j]*DD + sf4*4);
        sw4[j] = *(const float4*)(Wg + (size_t)srow[j]*DD + sf4*4);
    }
    {
        uint32_t* Ah = smw;             uint32_t* Al = smw + P_ARR;
        uint32_t* Wh = smw + 2*P_ARR;   uint32_t* Wl = smw + 3*P_ARR;
        #pragma unroll
        for (int j = 0; j < 4; j++) {
            int wbase = srow[j]*P_PITCH + sf4*2;
            float4 v = sa[j];
            Ah[wbase]   = pack_bf16(v.x, v.y);
            Ah[wbase+1] = pack_bf16(v.z, v.w);
            Al[wbase]   = pack_bf16(v.x - bf16_hi(v.x), v.y - bf16_hi(v.y));
            Al[wbase+1] = pack_bf16(v.z - bf16_hi(v.z), v.w - bf16_hi(v.w));
            v = sw4[j];
            Wh[wbase]   = pack_bf16(v.x, v.y);
            Wh[wbase+1] = pack_bf16(v.z, v.w);
            Wl[wbase]   = pack_bf16(v.x - bf16_hi(v.x), v.y - bf16_hi(v.y));
            Wl[wbase+1] = pack_bf16(v.z - bf16_hi(v.z), v.w - bf16_hi(v.w));
        }
    }
    __syncthreads();

    for (int c = 0; c < 32; c++) {
        const int buf = c & 1;
        if (c + 1 < 32) {
            const int kc = (c + 1) * 32;
            #pragma unroll
            for (int j = 0; j < 4; j++) {
                sa[j]  = *(const float4*)(Ag + (size_t)srow[j]*DD + kc + sf4*4);
                sw4[j] = *(const float4*)(Wg + (size_t)srow[j]*DD + kc + sf4*4);
            }
        }
        {
            const uint32_t* Ah = smw + (buf*4 + 0)*P_ARR;
            const uint32_t* Al = smw + (buf*4 + 1)*P_ARR;
            const uint32_t* Wh = smw + (buf*4 + 2)*P_ARR;
            const uint32_t* Wl = smw + (buf*4 + 3)*P_ARR;
            #pragma unroll
            for (int ks = 0; ks < 2; ks++) {
                const int kw = (lane & 3) + ks*8;
                uint32_t ah[4][4], al[4][4];
                #pragma unroll
                for (int mt = 0; mt < 4; mt++) {
                    int r = wm*64 + mt*16 + (lane >> 2);
                    int b0 = r*P_PITCH + kw;
                    ah[mt][0] = Ah[b0];       ah[mt][1] = Ah[b0 + 8*P_PITCH];
                    ah[mt][2] = Ah[b0 + 4];   ah[mt][3] = Ah[b0 + 8*P_PITCH + 4];
                    al[mt][0] = Al[b0];       al[mt][1] = Al[b0 + 8*P_PITCH];
                    al[mt][2] = Al[b0 + 4];   al[mt][3] = Al[b0 + 8*P_PITCH + 4];
                }
                uint32_t bh[4][2], bl[4][2];
                #pragma unroll
                for (int nt = 0; nt < 4; nt++) {
                    int rn = wn*32 + nt*8 + (lane >> 2);
                    int b0 = rn*P_PITCH + kw;
                    bh[nt][0] = Wh[b0]; bh[nt][1] = Wh[b0 + 4];
                    bl[nt][0] = Wl[b0]; bl[nt][1] = Wl[b0 + 4];
                }
                #pragma unroll
                for (int mt = 0; mt < 4; mt++)
                    #pragma unroll
                    for (int nt = 0; nt < 4; nt++) {
                        mma_bf16(acc[mt][nt], ah[mt][0], ah[mt][1], ah[mt][2], ah[mt][3],
                                 bh[nt][0], bh[nt][1]);
                        mma_bf16(acc[mt][nt], ah[mt][0], ah[mt][1], ah[mt][2], ah[mt][3],
                                 bl[nt][0], bl[nt][1]);
                        mma_bf16(acc[mt][nt], al[mt][0], al[mt][1], al[mt][2], al[mt][3],
                                 bh[nt][0], bh[nt][1]);
                    }
            }
        }
        if (c + 1 < 32) {
            const int ob = 1 - buf;
            uint32_t* Ah = smw + (ob*4 + 0)*P_ARR;
            uint32_t* Al = smw + (ob*4 + 1)*P_ARR;
            uint32_t* Wh = smw + (ob*4 + 2)*P_ARR;
            uint32_t* Wl = smw + (ob*4 + 3)*P_ARR;
            #pragma unroll
            for (int j = 0; j < 4; j++) {
                int wbase = srow[j]*P_PITCH + sf4*2;
                float4 v = sa[j];
                Ah[wbase]   = pack_bf16(v.x, v.y);
                Ah[wbase+1] = pack_bf16(v.z, v.w);
                Al[wbase]   = pack_bf16(v.x - bf16_hi(v.x), v.y - bf16_hi(v.y));
                Al[wbase+1] = pack_bf16(v.z - bf16_hi(v.z), v.w - bf16_hi(v.w));
                v = sw4[j];
                Wh[wbase]   = pack_bf16(v.x, v.y);
                Wh[wbase+1] = pack_bf16(v.z, v.w);
                Wl[wbase]   = pack_bf16(v.x - bf16_hi(v.x), v.y - bf16_hi(v.y));
                Wl[wbase+1] = pack_bf16(v.z - bf16_hi(v.z), v.w - bf16_hi(v.w));
            }
        }
        __syncthreads();
    }

    const float* bp = (nreg == 0) ? bq : (nreg == 1) ? bk : bv;
    float* baseO;
    int Mrows, moff;
    if (!isRe) {
        baseO = (nreg == 0) ? outQ : (nreg == 1) ? outK : outV;
        Mrows = 4096; moff = m0;
    } else {
        baseO = (nreg == 0) ? outPQ : outPK;
        Mrows = 1024; moff = m0 - 4096;
    }

    #pragma unroll
    for (int mt = 0; mt < 4; mt++) {
        int m = moff + wm*64 + mt*16 + (lane >> 2);
        #pragma unroll
        for (int nt = 0; nt < 4; nt++) {
            int ncl = (n0 & 1023) + wn*32 + nt*8 + (lane & 3)*2;
            int hh = ncl >> 6, w = ncl & 63;
            float bx = bp[ncl], by = bp[ncl + 1];
            float* d0 = baseO + ((size_t)hh*Mrows + m)*64 + w;
            float2 v0 = { acc[mt][nt][0] + bx, acc[mt][nt][1] + by };
            float2 v1 = { acc[mt][nt][2] + bx, acc[mt][nt][3] + by };
            *(float2*)d0 = v0;
            *(float2*)(d0 + 8*64) = v1;
        }
    }
}

// ===========================================================================
// Bias table GEMM — single bf16 product, bf16 output, DIAGONAL-BAND SKIP.
//   tbl 0: C2P[h,m,r] = Q[h,m,:]·PK[h,r,:];  tbl 1: P2C = K·PQ
// Attn only gathers r = i-j+511 (j,i in [0,512)); per 128-row m-block the
// needed r range is width 639 -> exactly 5 of 8 n-blocks. Skip the rest.
// ===========================================================================
#define T_PITCH 36
#define T_ARR   (128*T_PITCH)
#define T_SMEM_BYTES (2*T_ARR*4)         // 36864

__global__ __launch_bounds__(256) void bias_table_kernel()
{
    const int m0 = blockIdx.x * 128;     // [0,4096)
    const int n0 = blockIdx.y * 128;     // [0,1024)
    const int h   = blockIdx.z & 15;
    const int tbl = blockIdx.z >> 4;

    // Band skip: rows i (tbl 0) need r in [i, i+511]; rows j (tbl 1) need
    // r in [511-j, 1022-j]. Over this block's 128 rows (m0_loc..m0_loc+127):
    const int m0_loc = m0 & 511;
    const int lo = tbl ? (384 - m0_loc) : m0_loc;
    const int hi = tbl ? (1022 - m0_loc) : (m0_loc + 638);
    if (n0 + 127 < lo || n0 > hi) return;

    extern __shared__ uint32_t smw[];
    const int tid  = threadIdx.x;
    const int lane = tid & 31;
    const int wid  = tid >> 5;
    const int wm   = wid >> 2;
    const int wn   = wid & 3;

    const float* Ag = (tbl ? g_K : g_Q) + ((size_t)h*4096 + m0) * WD;
    const float* Bg = (tbl ? g_PQ : g_PK) + ((size_t)h*1024 + n0) * WD;
    __nv_bfloat16* Cg = (tbl ? g_P2C : g_C2P) + (size_t)h*4096*1024;

    uint32_t* Ah = smw;
    uint32_t* Bh = smw + T_ARR;

    #pragma unroll
    for (int v = 0; v < 8; v++) {
        int idx = v*256 + tid;
        int row = idx >> 4;
        int cw  = idx & 15;
        int wbase = row*T_PITCH + cw*2;
        float4 a = *(const float4*)(Ag + (size_t)row*WD + cw*4);
        Ah[wbase]   = pack_bf16(a.x, a.y);
        Ah[wbase+1] = pack_bf16(a.z, a.w);
        float4 b = *(const float4*)(Bg + (size_t)row*WD + cw*4);
        Bh[wbase]   = pack_bf16(b.x, b.y);
        Bh[wbase+1] = pack_bf16(b.z, b.w);
    }
    __syncthreads();

    float acc[4][4][4] = {};
    #pragma unroll
    for (int ks = 0; ks < 4; ks++) {
        const int kw = (lane & 3) + ks*8;
        uint32_t ah[4][4];
        #pragma unroll
        for (int mt = 0; mt < 4; mt++) {
            int r = wm*64 + mt*16 + (lane >> 2);
            int b0 = r*T_PITCH + kw;
            ah[mt][0] = Ah[b0];       ah[mt][1] = Ah[b0 + 8*T_PITCH];
            ah[mt][2] = Ah[b0 + 4];   ah[mt][3] = Ah[b0 + 8*T_PITCH + 4];
        }
        uint32_t bh[4][2];
        #pragma unroll
        for (int nt = 0; nt < 4; nt++) {
            int rn = wn*32 + nt*8 + (lane >> 2);
            int b0 = rn*T_PITCH + kw;
            bh[nt][0] = Bh[b0]; bh[nt][1] = Bh[b0 + 4];
        }
        #pragma unroll
        for (int mt = 0; mt < 4; mt++)
            #pragma unroll
            for (int nt = 0; nt < 4; nt++)
                mma_bf16(acc[mt][nt], ah[mt][0], ah[mt][1], ah[mt][2], ah[mt][3],
                         bh[nt][0], bh[nt][1]);
    }

    #pragma unroll
    for (int mt = 0; mt < 4; mt++) {
        int m = m0 + wm*64 + mt*16 + (lane >> 2);
        #pragma unroll
        for (int nt = 0; nt < 4; nt++) {
            int ncl = n0 + wn*32 + nt*8 + (lane & 3)*2;
            __nv_bfloat16* d0 = Cg + (size_t)m*1024 + ncl;
            *(uint32_t*)d0 = pack_bf16(acc[mt][nt][0], acc[mt][nt][1]);
            *(uint32_t*)(d0 + 8*1024) = pack_bf16(acc[mt][nt][2], acc[mt][nt][3]);
        }
    }
}

// ===========================================================================
// HMMA flash attention, occupancy-3 (round-8/11, known good).
// CTA = 64 i-rows (4 warps, m16 each), 128 threads, smem 70.7 KB.
// ===========================================================================
#define AQ_P 36
#define CP_P 66
#define W_KH 0
#define W_KL (W_KH + 64*AQ_P)            // 2304
#define W_VH (W_KL + 64*AQ_P)            // 4608
#define W_VL (W_VH + 64*AQ_P)            // 6912
#define W_C2 (W_VL + 64*AQ_P)            // 9216  (fp32 [di][jl] pitch 66)
#define W_P2 (W_C2 + 64*CP_P)            // 13440 (fp32 [jl][di] pitch 66)
#define ATTN_WORDS (W_P2 + 64*CP_P)      // 17664
#define ATTN_SMEM_BYTES (ATTN_WORDS*4)   // 70656
#define W_QH W_C2
#define W_QL (W_C2 + 64*AQ_P)

__global__ __launch_bounds__(128, 3) void attn_mma_kernel(float* __restrict__ out)
{
    extern __shared__ uint32_t smw[];
    float* fC2P = (float*)(smw + W_C2);
    float* fP2C = (float*)(smw + W_P2);

    const int h  = blockIdx.z;
    const int b  = blockIdx.y;
    const int i0 = blockIdx.x * 64;
    const int tid  = threadIdx.x;
    const int lane = tid & 31;
    const int warp = tid >> 5;     // 0..3
    const int g = lane >> 2;       // row within m16 half
    const int t = lane & 3;        // col quad index

    const float* Qg  = g_Q + ((size_t)(h*BB + b)*SLEN + i0)*WD;
    const float* Kg  = g_K + (size_t)(h*BB + b)*SLEN*WD;
    const float* Vg  = g_V + (size_t)(h*BB + b)*SLEN*WD;
    const __nv_bfloat16* C2Pg = g_C2P + ((size_t)h*4096 + (size_t)b*512)*1024;
    const __nv_bfloat16* P2Cg = g_P2C + ((size_t)h*4096 + (size_t)b*512)*1024;

    // ---- Stage Q (aliased region) and cache a-fragments ----
    for (int idx = tid; idx < 1024; idx += 128) {
        int r = idx >> 4, c4 = (idx & 15) << 2;
        float4 v = *(const float4*)(Qg + r*WD + c4);
        int wb = r*AQ_P + (c4 >> 1);
        smw[W_QH + wb]     = pack_bf16(v.x, v.y);
        smw[W_QH + wb + 1] = pack_bf16(v.z, v.w);
        smw[W_QL + wb]     = pack_bf16(v.x - bf16_hi(v.x), v.y - bf16_hi(v.y));
        smw[W_QL + wb + 1] = pack_bf16(v.z - bf16_hi(v.z), v.w - bf16_hi(v.w));
    }
    __syncthreads();

    uint32_t qh[4][4], ql[4][4];
    {
        const int r0w = (16*warp + g)*AQ_P;
        const int r1w = (16*warp + g + 8)*AQ_P;
        #pragma unroll
        for (int ks = 0; ks < 4; ks++) {
            int o0 = 8*ks + t;
            qh[ks][0] = smw[W_QH + r0w + o0];     qh[ks][1] = smw[W_QH + r1w + o0];
            qh[ks][2] = smw[W_QH + r0w + o0 + 4]; qh[ks][3] = smw[W_QH + r1w + o0 + 4];
            ql[ks][0] = smw[W_QL + r0w + o0];     ql[ks][1] = smw[W_QL + r1w + o0];
            ql[ks][2] = smw[W_QL + r0w + o0 + 4]; ql[ks][3] = smw[W_QL + r1w + o0 + 4];
        }
    }

    float o[8][4] = {};
    float m0 = -1e30f, m1 = -1e30f, l0 = 0.f, l1 = 0.f;
    const float L2S = rsqrtf(192.0f) * 1.44269504f;
    const int r0 = 16*warp + g;

    for (int jt = 0; jt < 8; jt++) {
        const int j0 = jt * 64;
        __syncthreads();   // prior tile reads complete (covers Q frag load at jt=0)

        // K hi/lo [j][w-pairs]
        for (int idx = tid; idx < 1024; idx += 128) {
            int r = idx >> 4, c4 = (idx & 15) << 2;
            float4 v = *(const float4*)(Kg + (j0 + r)*WD + c4);
            int wb = r*AQ_P + (c4 >> 1);
            smw[W_KH + wb]     = pack_bf16(v.x, v.y);
            smw[W_KH + wb + 1] = pack_bf16(v.z, v.w);
            smw[W_KL + wb]     = pack_bf16(v.x - bf16_hi(v.x), v.y - bf16_hi(v.y));
            smw[W_KL + wb + 1] = pack_bf16(v.z - bf16_hi(v.z), v.w - bf16_hi(v.w));
        }
        // V transposed hi/lo [w][j-pairs]
        for (int idx = tid; idx < 512; idx += 128) {
            int jp = idx & 31, c4 = (idx >> 5) << 2;
            const float* v0p = Vg + (j0 + 2*jp)*WD + c4;
            float4 a = *(const float4*)v0p;
            float4 c = *(const float4*)(v0p + WD);
            smw[W_VH + (c4+0)*AQ_P + jp] = pack_bf16(a.x, c.x);
            smw[W_VH + (c4+1)*AQ_P + jp] = pack_bf16(a.y, c.y);
            smw[W_VH + (c4+2)*AQ_P + jp] = pack_bf16(a.z, c.z);
            smw[W_VH + (c4+3)*AQ_P + jp] = pack_bf16(a.w, c.w);
            smw[W_VL + (c4+0)*AQ_P + jp] = pack_bf16(a.x - bf16_hi(a.x), c.x - bf16_hi(c.x));
            smw[W_VL + (c4+1)*AQ_P + jp] = pack_bf16(a.y - bf16_hi(a.y), c.y - bf16_hi(c.y));
            smw[W_VL + (c4+2)*AQ_P + jp] = pack_bf16(a.z - bf16_hi(a.z), c.z - bf16_hi(c.z));
            smw[W_VL + (c4+3)*AQ_P + jp] = pack_bf16(a.w - bf16_hi(a.w), c.w - bf16_hi(c.w));
        }
        // C2P gather [di][jl] (reversed-j bf16 reads)
        for (int idx = tid; idx < 1024; idx += 128) {
            int di = idx >> 4, jg = idx & 15;
            const __nv_bfloat16* src = C2Pg + (size_t)(i0 + di)*1024
                                       + (i0 + di) - j0 + 511 - 4*jg;
            float* dst = fC2P + di*CP_P + 4*jg;
            dst[0] = __bfloat162float(src[0]);
            dst[1] = __bfloat162float(src[-1]);
            dst[2] = __bfloat162float(src[-2]);
            dst[3] = __bfloat162float(src[-3]);
        }
        // P2C gather [jl][di] (contiguous along di)
        for (int idx = tid; idx < 4096; idx += 128) {
            int jl = idx >> 6, di = idx & 63;
            fP2C[jl*CP_P + di] = __bfloat162float(
                P2Cg[(size_t)(j0 + jl)*1024 + i0 - j0 - jl + 511 + di]);
        }
        __syncthreads();

        // ---- S = Q K^T (split bf16, 3 products) ----
        float s[8][4];
        #pragma unroll
        for (int nt = 0; nt < 8; nt++) {
            float c[4] = {0.f, 0.f, 0.f, 0.f};
            #pragma unroll
            for (int ks = 0; ks < 4; ks++) {
                int kb = (8*nt + g)*AQ_P + 8*ks + t;
                uint32_t bh0 = smw[W_KH + kb], bh1 = smw[W_KH + kb + 4];
                uint32_t bl0 = smw[W_KL + kb], bl1 = smw[W_KL + kb + 4];
                mma_bf16(c, qh[ks][0], qh[ks][1], qh[ks][2], qh[ks][3], bh0, bh1);
                mma_bf16(c, qh[ks][0], qh[ks][1], qh[ks][2], qh[ks][3], bl0, bl1);
                mma_bf16(c, ql[ks][0], ql[ks][1], ql[ks][2], ql[ks][3], bh0, bh1);
            }
            s[nt][0] = c[0]; s[nt][1] = c[1]; s[nt][2] = c[2]; s[nt][3] = c[3];
        }

        // ---- bias add + scale (log2 domain) ----
        #pragma unroll
        for (int nt = 0; nt < 8; nt++) {
            int cb = 8*nt + 2*t;
            float2 cA = *(const float2*)(fC2P + r0*CP_P + cb);
            float2 cB = *(const float2*)(fC2P + (r0+8)*CP_P + cb);
            float pA0 = fP2C[cb*CP_P + r0],     pA1 = fP2C[(cb+1)*CP_P + r0];
            float pB0 = fP2C[cb*CP_P + r0 + 8], pB1 = fP2C[(cb+1)*CP_P + r0 + 8];
            s[nt][0] = (s[nt][0] + cA.x + pA0) * L2S;
            s[nt][1] = (s[nt][1] + cA.y + pA1) * L2S;
            s[nt][2] = (s[nt][2] + cB.x + pB0) * L2S;
            s[nt][3] = (s[nt][3] + cB.y + pB1) * L2S;
        }

        // ---- online softmax (quad reduce) ----
        float mx0 = -1e30f, mx1 = -1e30f;
        #pragma unroll
        for (int nt = 0; nt < 8; nt++) {
            mx0 = fmaxf(mx0, fmaxf(s[nt][0], s[nt][1]));
            mx1 = fmaxf(mx1, fmaxf(s[nt][2], s[nt][3]));
        }
        mx0 = fmaxf(mx0, __shfl_xor_sync(0xffffffffu, mx0, 1));
        mx0 = fmaxf(mx0, __shfl_xor_sync(0xffffffffu, mx0, 2));
        mx1 = fmaxf(mx1, __shfl_xor_sync(0xffffffffu, mx1, 1));
        mx1 = fmaxf(mx1, __shfl_xor_sync(0xffffffffu, mx1, 2));
        float mn0 = fmaxf(m0, mx0), mn1 = fmaxf(m1, mx1);
        float cr0 = ex2f(m0 - mn0), cr1 = ex2f(m1 - mn1);
        float rs0 = 0.f, rs1 = 0.f;
        #pragma unroll
        for (int nt = 0; nt < 8; nt++) {
            s[nt][0] = ex2f(s[nt][0] - mn0);
            s[nt][1] = ex2f(s[nt][1] - mn0);
            s[nt][2] = ex2f(s[nt][2] - mn1);
            s[nt][3] = ex2f(s[nt][3] - mn1);
            rs0 += s[nt][0] + s[nt][1];
            rs1 += s[nt][2] + s[nt][3];
        }
        rs0 += __shfl_xor_sync(0xffffffffu, rs0, 1);
        rs0 += __shfl_xor_sync(0xffffffffu, rs0, 2);
        rs1 += __shfl_xor_sync(0xffffffffu, rs1, 1);
        rs1 += __shfl_xor_sync(0xffffffffu, rs1, 2);
        l0 = l0*cr0 + rs0;  l1 = l1*cr1 + rs1;
        m0 = mn0;  m1 = mn1;
        #pragma unroll
        for (int nt = 0; nt < 8; nt++) {
            o[nt][0] *= cr0; o[nt][1] *= cr0;
            o[nt][2] *= cr1; o[nt][3] *= cr1;
        }

        // ---- O += P V (C-frag -> A-frag in registers, 3 products) ----
        #pragma unroll
        for (int kt = 0; kt < 4; kt++) {
            float p00 = s[2*kt][0],   p01 = s[2*kt][1];
            float p02 = s[2*kt][2],   p03 = s[2*kt][3];
            float p10 = s[2*kt+1][0], p11 = s[2*kt+1][1];
            float p12 = s[2*kt+1][2], p13 = s[2*kt+1][3];
            uint32_t pa0 = pack_bf16(p00, p01), pa1 = pack_bf16(p02, p03);
            uint32_t pa2 = pack_bf16(p10, p11), pa3 = pack_bf16(p12, p13);
            uint32_t pl0 = pack_bf16(p00 - bf16_hi(p00), p01 - bf16_hi(p01));
            uint32_t pl1 = pack_bf16(p02 - bf16_hi(p02), p03 - bf16_hi(p03));
            uint32_t pl2 = pack_bf16(p10 - bf16_hi(p10), p11 - bf16_hi(p11));
            uint32_t pl3 = pack_bf16(p12 - bf16_hi(p12), p13 - bf16_hi(p13));
            #pragma unroll
            for (int nw = 0; nw < 8; nw++) {
                int vb = (8*nw + g)*AQ_P + 8*kt + t;
                uint32_t vh0 = smw[W_VH + vb], vh1 = smw[W_VH + vb + 4];
                uint32_t vl0 = smw[W_VL + vb], vl1 = smw[W_VL + vb + 4];
                mma_bf16(o[nw], pa0, pa1, pa2, pa3, vh0, vh1);
                mma_bf16(o[nw], pa0, pa1, pa2, pa3, vl0, vl1);
                mma_bf16(o[nw], pl0, pl1, pl2, pl3, vh0, vh1);
            }
        }
    }

    // ---- epilogue ----
    float inv0 = 1.0f / l0, inv1 = 1.0f / l1;
    #pragma unroll
    for (int nw = 0; nw < 8; nw++) {
        int wcol = h*64 + 8*nw + 2*t;
        float* d0 = out + ((size_t)b*SLEN + i0 + r0)*DD + wcol;
        *(float2*)d0 = make_float2(o[nw][0]*inv0, o[nw][1]*inv0);
        *(float2*)(d0 + 8*DD) = make_float2(o[nw][2]*inv1, o[nw][3]*inv1);
    }
}

// ===========================================================================
// Launch (round-11 schedule): projA -> fork { projV || tables } -> join -> attn
// ===========================================================================
extern "C" void kernel_launch(void* const* d_in, const int* in_sizes, int n_in,
                              void* d_out, int out_size)
{
    (void)in_sizes; (void)n_in; (void)out_size;
    const float* x  = (const float*)d_in[0];
    const float* re = (const float*)d_in[1];
    const float* Wq = (const float*)d_in[2];
    const float* bq = (const float*)d_in[3];
    const float* Wk = (const float*)d_in[4];
    const float* bk = (const float*)d_in[5];
    const float* Wv = (const float*)d_in[6];
    const float* bv = (const float*)d_in[7];
    float* out = (float*)d_out;

    void *qp, *kp, *vp, *pkp, *pqp;
    cudaGetSymbolAddress(&qp,  g_Q);
    cudaGetSymbolAddress(&kp,  g_K);
    cudaGetSymbolAddress(&vp,  g_V);
    cudaGetSymbolAddress(&pkp, g_PK);
    cudaGetSymbolAddress(&pqp, g_PQ);

    cudaFuncSetAttribute(proj_mma_kernel, cudaFuncAttributeMaxDynamicSharedMemorySize,
                         P_SMEM_BYTES);
    cudaFuncSetAttribute(bias_table_kernel, cudaFuncAttributeMaxDynamicSharedMemorySize,
                         T_SMEM_BYTES);
    cudaFuncSetAttribute(attn_mma_kernel, cudaFuncAttributeMaxDynamicSharedMemorySize,
                         ATTN_SMEM_BYTES);

    cudaStream_t s2;
    cudaEvent_t eFork, eJoin;
    cudaStreamCreateWithFlags(&s2, cudaStreamNonBlocking);
    cudaEventCreateWithFlags(&eFork, cudaEventDisableTiming);
    cudaEventCreateWithFlags(&eJoin, cudaEventDisableTiming);

    // projA: Q,K projections + pos_q,pos_k (n-blocks 0..15, all 5120 rows)
    proj_mma_kernel<<<dim3(40, 16), dim3(256), P_SMEM_BYTES>>>(
        x, re, Wq, bq, Wk, bk, Wv, bv,
        (float*)qp, (float*)kp, (float*)vp, (float*)pkp, (float*)pqp, 0);

    cudaEventRecord(eFork, 0);
    cudaStreamWaitEvent(s2, eFork, 0);

    // projV on side stream (n-blocks 16..23, x rows only)
    proj_mma_kernel<<<dim3(32, 8), dim3(256), P_SMEM_BYTES, s2>>>(
        x, re, Wq, bq, Wk, bk, Wv, bv,
        (float*)qp, (float*)kp, (float*)vp, (float*)pkp, (float*)pqp, 16);

    // bias tables on main stream (needs only Q,K,PK,PQ from projA)
    bias_table_kernel<<<dim3(32, 8, 32), dim3(256), T_SMEM_BYTES>>>();

    // join
    cudaEventRecord(eJoin, s2);
    cudaStreamWaitEvent(0, eJoin, 0);

    attn_mma_kernel<<<dim3(8, BB, HH), dim3(128), ATTN_SMEM_BYTES>>>(out);
}